// round 1
// baseline (speedup 1.0000x reference)
#include <cuda_runtime.h>

// Scratch: K projection (B*L x D) and attention output (B*L x D), fp32.
__device__ float g_K[4096 * 1024];
__device__ float g_att[4096 * 1024];

__device__ __forceinline__ float fast_exp2(float x) {
    float y;
    asm("ex2.approx.ftz.f32 %0, %1;" : "=f"(y) : "f"(x));
    return y;
}

// ---------------------------------------------------------------------------
// Tiled SGEMM: C[M,N] = A[M,1024] @ B[1024,N] + bias[N]
//   A row-major lda=1024, B row-major with ldb (3072 for W_attn slice, 1024
//   for W_proj), C row-major ldc=1024. BM=BN=64, BK=16, 256 threads,
//   4x4 accumulators per thread with strided (q, q+16, q+32, q+48) mapping so
//   As/Bs reads are broadcast / conflict-free with stride-65 padding.
// ---------------------------------------------------------------------------
__global__ __launch_bounds__(256) void gemm_kernel(
    const float* __restrict__ A, const float* __restrict__ B,
    const float* __restrict__ bias, float* __restrict__ C,
    int ldb)
{
    __shared__ float As[16 * 65];  // As[k][m], padded
    __shared__ float Bs[16 * 65];  // Bs[k][n], padded

    const int tid = threadIdx.x;
    const int tx = tid & 15;
    const int ty = tid >> 4;
    const int n0 = blockIdx.x * 64;
    const int m0 = blockIdx.y * 64;

    float acc[4][4];
#pragma unroll
    for (int i = 0; i < 4; i++)
#pragma unroll
        for (int j = 0; j < 4; j++) acc[i][j] = 0.0f;

    for (int kt = 0; kt < 1024; kt += 16) {
        // Load A tile 64x16 transposed into As[k][m]
#pragma unroll
        for (int p = 0; p < 4; p++) {
            int m = (tid >> 4) + p * 16;
            int k = tid & 15;
            As[k * 65 + m] = A[(m0 + m) * 1024 + kt + k];
        }
        // Load B tile 16x64 into Bs[k][n]
#pragma unroll
        for (int p = 0; p < 4; p++) {
            int k = (tid >> 6) + p * 4;
            int n = tid & 63;
            Bs[k * 65 + n] = B[(kt + k) * ldb + n0 + n];
        }
        __syncthreads();

#pragma unroll
        for (int k = 0; k < 16; k++) {
            float a[4], b[4];
#pragma unroll
            for (int i = 0; i < 4; i++) a[i] = As[k * 65 + ty + 16 * i];
#pragma unroll
            for (int j = 0; j < 4; j++) b[j] = Bs[k * 65 + tx + 16 * j];
#pragma unroll
            for (int i = 0; i < 4; i++)
#pragma unroll
                for (int j = 0; j < 4; j++) acc[i][j] = fmaf(a[i], b[j], acc[i][j]);
        }
        __syncthreads();
    }

#pragma unroll
    for (int j = 0; j < 4; j++) {
        int n = n0 + tx + 16 * j;
        float bv = bias[n];
#pragma unroll
        for (int i = 0; i < 4; i++) {
            int m = m0 + ty + 16 * i;
            C[m * 1024 + n] = acc[i][j] + bv;
        }
    }
}

// ---------------------------------------------------------------------------
// Fused flash attention over K (Q == K here): per (b, h), 64-query blocks,
// 64-key tiles, online softmax, fp32.
//   K layout: g_K[(b*2048 + l)*1024 + h*64 + d]
//   Out written directly in (B, L, H*Dh) layout for the proj GEMM.
// ---------------------------------------------------------------------------
__global__ __launch_bounds__(256) void attn_kernel(
    const float* __restrict__ K, float* __restrict__ Out)
{
    extern __shared__ float sm[];
    float* Qt = sm;                 // [64][65]  Qt[d][q] (pre-scaled)
    float* Kt = sm + 64 * 65;       // [64][65]  Kt[d][j]
    float* Kn = sm + 2 * 64 * 65;   // [64][65]  Kn[j][d]
    float* Pt = sm + 3 * 64 * 65;   // [64][65]  Pt[j][q]

    const int tid = threadIdx.x;
    const int tx = tid & 15;
    const int ty = tid >> 4;
    const int b = blockIdx.y >> 4;
    const int h = blockIdx.y & 15;
    const int q0 = blockIdx.x * 64;

    const float* Kb = K + (size_t)b * 2048 * 1024 + h * 64;

    // scale = 1/sqrt(64) folded with log2(e) so softmax uses exp2
    const float QSCALE = 0.125f * 1.4426950408889634f;

    // Load Q tile transposed (coalesced global, conflict-free smem).
#pragma unroll
    for (int p = 0; p < 16; p++) {
        int i = tid + p * 256;
        int q = i >> 6, d = i & 63;
        Qt[d * 65 + q] = Kb[(q0 + q) * 1024 + d] * QSCALE;
    }

    float m_i[4], l_i[4], Oacc[4][4];
#pragma unroll
    for (int i = 0; i < 4; i++) {
        m_i[i] = -1e30f;
        l_i[i] = 0.0f;
#pragma unroll
        for (int d = 0; d < 4; d++) Oacc[i][d] = 0.0f;
    }

    for (int k0 = 0; k0 < 2048; k0 += 64) {
        __syncthreads();  // previous iteration done with Kn/Kt/Pt
        // Load K tile in both layouts (single global read).
#pragma unroll
        for (int p = 0; p < 16; p++) {
            int i = tid + p * 256;
            int j = i >> 6, d = i & 63;
            float v = Kb[(k0 + j) * 1024 + d];
            Kn[j * 65 + d] = v;
            Kt[d * 65 + j] = v;
        }
        __syncthreads();

        // S tile: s[i][j] = sum_d Qt[d][q] * Kt[d][k]
        float s[4][4];
#pragma unroll
        for (int i = 0; i < 4; i++)
#pragma unroll
            for (int j = 0; j < 4; j++) s[i][j] = 0.0f;

#pragma unroll 8
        for (int d = 0; d < 64; d++) {
            float a[4], bb[4];
#pragma unroll
            for (int i = 0; i < 4; i++) a[i] = Qt[d * 65 + ty + 16 * i];
#pragma unroll
            for (int j = 0; j < 4; j++) bb[j] = Kt[d * 65 + tx + 16 * j];
#pragma unroll
            for (int i = 0; i < 4; i++)
#pragma unroll
                for (int j = 0; j < 4; j++) s[i][j] = fmaf(a[i], bb[j], s[i][j]);
        }

        // Online softmax per query row (row spread over 16 lanes).
#pragma unroll
        for (int i = 0; i < 4; i++) {
            float mx = fmaxf(fmaxf(s[i][0], s[i][1]), fmaxf(s[i][2], s[i][3]));
            mx = fmaxf(mx, __shfl_xor_sync(0xffffffffu, mx, 1));
            mx = fmaxf(mx, __shfl_xor_sync(0xffffffffu, mx, 2));
            mx = fmaxf(mx, __shfl_xor_sync(0xffffffffu, mx, 4));
            mx = fmaxf(mx, __shfl_xor_sync(0xffffffffu, mx, 8));
            float mnew = fmaxf(m_i[i], mx);
            float corr = fast_exp2(m_i[i] - mnew);
            float rs = 0.0f;
#pragma unroll
            for (int j = 0; j < 4; j++) {
                s[i][j] = fast_exp2(s[i][j] - mnew);
                rs += s[i][j];
            }
            rs += __shfl_xor_sync(0xffffffffu, rs, 1);
            rs += __shfl_xor_sync(0xffffffffu, rs, 2);
            rs += __shfl_xor_sync(0xffffffffu, rs, 4);
            rs += __shfl_xor_sync(0xffffffffu, rs, 8);
            l_i[i] = l_i[i] * corr + rs;
            m_i[i] = mnew;
#pragma unroll
            for (int d = 0; d < 4; d++) Oacc[i][d] *= corr;
            // Stage P transposed for the AV GEMM.
#pragma unroll
            for (int j = 0; j < 4; j++)
                Pt[(tx + 16 * j) * 65 + (ty + 16 * i)] = s[i][j];
        }
        __syncthreads();

        // O += P @ Ktile : Oacc[i][d] += Pt[j][q] * Kn[j][d]
#pragma unroll 8
        for (int j = 0; j < 64; j++) {
            float a[4], bb[4];
#pragma unroll
            for (int i = 0; i < 4; i++) a[i] = Pt[j * 65 + ty + 16 * i];
#pragma unroll
            for (int d = 0; d < 4; d++) bb[d] = Kn[j * 65 + tx + 16 * d];
#pragma unroll
            for (int i = 0; i < 4; i++)
#pragma unroll
                for (int d = 0; d < 4; d++) Oacc[i][d] = fmaf(a[i], bb[d], Oacc[i][d]);
        }
    }

    // Normalize and write in (B, L, D) layout.
#pragma unroll
    for (int i = 0; i < 4; i++) {
        float inv = 1.0f / l_i[i];
        int q = q0 + ty + 16 * i;
#pragma unroll
        for (int d = 0; d < 4; d++) {
            Out[((size_t)b * 2048 + q) * 1024 + h * 64 + tx + 16 * d] = Oacc[i][d] * inv;
        }
    }
}

extern "C" void kernel_launch(void* const* d_in, const int* in_sizes, int n_in,
                              void* d_out, int out_size) {
    const float* x      = (const float*)d_in[0];  // (2, 2048, 1024)
    const float* W_attn = (const float*)d_in[1];  // (1024, 3072)
    const float* b_attn = (const float*)d_in[2];  // (3072,)
    const float* W_proj = (const float*)d_in[3];  // (1024, 1024)
    const float* b_proj = (const float*)d_in[4];  // (1024,)
    float* out = (float*)d_out;                   // (2, 2048, 1024)

    float *gK, *gA;
    cudaGetSymbolAddress((void**)&gK, g_K);
    cudaGetSymbolAddress((void**)&gA, g_att);

    const int ATTN_SMEM = 4 * 64 * 65 * (int)sizeof(float);  // 66560 B
    cudaFuncSetAttribute(attn_kernel,
                         cudaFuncAttributeMaxDynamicSharedMemorySize, ATTN_SMEM);

    dim3 gemm_grid(1024 / 64, 4096 / 64);  // (N tiles, M tiles)

    // Stage 1: K = x @ W_attn[:, D:2D] + b_attn[D:2D]   (only K slice is used)
    gemm_kernel<<<gemm_grid, 256>>>(x, W_attn + 1024, b_attn + 1024, gK, 3072);

    // Stage 2: per-(b,h) softmax(K K^T / sqrt(Dh)) K, fused flash style.
    attn_kernel<<<dim3(2048 / 64, 32), 256, ATTN_SMEM>>>(gK, gA);

    // Stage 3: out = att @ W_proj + b_proj
    gemm_kernel<<<gemm_grid, 256>>>(gA, W_proj, b_proj, out, 1024);
}